// round 8
// baseline (speedup 1.0000x reference)
#include <cuda_runtime.h>
#include <stdint.h>

// embeddings: [B=32, L=4, W=512, D=768] f32; segment_ids: [B=32, W=512] i32 sorted/row.
// Out (f32, concat): word [B, D, W] then sent [B, D].
//
// word[b,d,s] = (1/L) * sum_{w: seg[b,w]==s} sum_l emb[b,l,w,d]
// sent[b,d]   = (1/W) * sum_s word[b,d,s]
//
// R7 change: branch-free main loop (smem RMW instead of run-flush branch),
// manual 2x unroll -> 8 independent LDG.128 per thread issue before any
// consumer; ptxas can front-batch loads across iterations.

#define BB 32
#define LL 4
#define WW 512
#define DD 768

#define TILE_S 16          // segments per block
#define NTHR   96          // threads per block
#define TILE_D (NTHR * 4)  // 384 d-channels per block (float4/thread)
#define STRIDE 388         // floats per smem row (97 f4; 97%8==1 -> STS.128 conflict-free)

__global__ void zero_sent_kernel(float* __restrict__ sent) {
    int i = blockIdx.x * blockDim.x + threadIdx.x;
    if (i < BB * DD) sent[i] = 0.0f;
}

__device__ __forceinline__ int lower_bound_smem(const int* a, int n, int v) {
    int lo = 0, hi = n;
    while (lo < hi) {
        int m = (lo + hi) >> 1;
        if (a[m] < v) lo = m + 1; else hi = m;
    }
    return lo;
}

__device__ __forceinline__ float4 sum4(float4 a, float4 b, float4 c, float4 d) {
    float4 r;
    r.x = (a.x + b.x) + (c.x + d.x);
    r.y = (a.y + b.y) + (c.y + d.y);
    r.z = (a.z + b.z) + (c.z + d.z);
    r.w = (a.w + b.w) + (c.w + d.w);
    return r;
}

__global__ __launch_bounds__(NTHR, 8)
void word_agg_kernel(const float* __restrict__ emb,
                     const int*   __restrict__ seg,
                     float*       __restrict__ word,   // [B, D, W]
                     float*       __restrict__ sent)   // [B, D]
{
    __shared__ float tile[TILE_S][STRIDE];  // 24,832 B
    __shared__ int   segs[WW];              // 2 KB

    const int b   = blockIdx.z;
    const int s0  = blockIdx.y * TILE_S;
    const int d0  = blockIdx.x * TILE_D;
    const int tid = threadIdx.x;

    #pragma unroll
    for (int i = tid; i < WW; i += NTHR) segs[i] = seg[b * WW + i];

    {   // zero the tile (empty segments must output 0)
        float4* t4 = (float4*)&tile[0][0];
        const int n4 = TILE_S * (STRIDE / 4);
        const float4 z = make_float4(0.f, 0.f, 0.f, 0.f);
        for (int i = tid; i < n4; i += NTHR) t4[i] = z;
    }
    __syncthreads();

    const int wlo = lower_bound_smem(segs, WW, s0);
    const int whi = lower_bound_smem(segs, WW, s0 + TILE_S);

    const int d = d0 + tid * 4;
    const float* __restrict__ base = emb + ((size_t)b * LL * WW) * DD + d;
    const size_t LSTRIDE = (size_t)WW * DD;

    // Branch-free accumulation: per-w layer-sum -> smem RMW at tile[seg-s0].
    // Each thread owns its f4 column, so plain LDS/STS (no atomics); same-
    // address back-to-back RMW is ordered by program order within the thread.
    int w = wlo;
    for (; w + 1 < whi; w += 2) {
        const float* p0 = base + (size_t)w * DD;
        const float* p1 = p0 + DD;
        // 8 independent LDG.128 — all issue before first consumer.
        float4 a0 = *(const float4*)(p0);
        float4 a1 = *(const float4*)(p0 + LSTRIDE);
        float4 a2 = *(const float4*)(p0 + 2 * LSTRIDE);
        float4 a3 = *(const float4*)(p0 + 3 * LSTRIDE);
        float4 b0 = *(const float4*)(p1);
        float4 b1 = *(const float4*)(p1 + LSTRIDE);
        float4 b2 = *(const float4*)(p1 + 2 * LSTRIDE);
        float4 b3 = *(const float4*)(p1 + 3 * LSTRIDE);
        const int i0 = segs[w]     - s0;
        const int i1 = segs[w + 1] - s0;
        float4 va = sum4(a0, a1, a2, a3);
        float4 vb = sum4(b0, b1, b2, b3);
        float4* r0 = (float4*)&tile[i0][0];
        float4 t0 = r0[tid];
        t0.x += va.x; t0.y += va.y; t0.z += va.z; t0.w += va.w;
        r0[tid] = t0;
        float4* r1 = (float4*)&tile[i1][0];
        float4 t1 = r1[tid];
        t1.x += vb.x; t1.y += vb.y; t1.z += vb.z; t1.w += vb.w;
        r1[tid] = t1;
    }
    if (w < whi) {
        const float* p0 = base + (size_t)w * DD;
        float4 a0 = *(const float4*)(p0);
        float4 a1 = *(const float4*)(p0 + LSTRIDE);
        float4 a2 = *(const float4*)(p0 + 2 * LSTRIDE);
        float4 a3 = *(const float4*)(p0 + 3 * LSTRIDE);
        const int i0 = segs[w] - s0;
        float4 va = sum4(a0, a1, a2, a3);
        float4* r0 = (float4*)&tile[i0][0];
        float4 t0 = r0[tid];
        t0.x += va.x; t0.y += va.y; t0.z += va.z; t0.w += va.w;
        r0[tid] = t0;
    }

    __syncthreads();

    // sent contribution: column sum over this s-tile.
    {
        float4 cs = make_float4(0.f, 0.f, 0.f, 0.f);
        #pragma unroll
        for (int s = 0; s < TILE_S; ++s) {
            float4 v = ((const float4*)&tile[s][0])[tid];
            cs.x += v.x; cs.y += v.y; cs.z += v.z; cs.w += v.w;
        }
        const float k = 0.25f / (float)WW;
        float* sp = sent + b * DD + d;
        atomicAdd(sp + 0, cs.x * k);
        atomicAdd(sp + 1, cs.y * k);
        atomicAdd(sp + 2, cs.z * k);
        atomicAdd(sp + 3, cs.w * k);
    }

    // Transposed coalesced write: word[b, d0+dd, s0 + ss4*4 .. +3] as float4.
    float* __restrict__ outb = word + ((size_t)b * DD + d0) * WW + s0;
    const int NOUT = (TILE_S / 4) * TILE_D;  // 1536 float4 stores
    for (int i2 = tid; i2 < NOUT; i2 += NTHR) {
        const int ss4 = i2 & 3;
        const int dd  = i2 >> 2;
        float4 v;
        v.x = 0.25f * tile[ss4 * 4 + 0][dd];
        v.y = 0.25f * tile[ss4 * 4 + 1][dd];
        v.z = 0.25f * tile[ss4 * 4 + 2][dd];
        v.w = 0.25f * tile[ss4 * 4 + 3][dd];
        *(float4*)(outb + (size_t)dd * WW + ss4 * 4) = v;
    }
}

extern "C" void kernel_launch(void* const* d_in, const int* in_sizes, int n_in,
                              void* d_out, int out_size) {
    const float* emb = (const float*)d_in[0];
    const int*   seg = (const int*)d_in[1];

    float* word = (float*)d_out;                   // [B, D, W]
    float* sent = word + (size_t)BB * DD * WW;     // [B, D]

    zero_sent_kernel<<<(BB * DD + 255) / 256, 256>>>(sent);

    dim3 grid(DD / TILE_D, WW / TILE_S, BB);       // (2, 32, 32) = 2048 blocks
    word_agg_kernel<<<grid, NTHR>>>(emb, seg, word, sent);
}

// round 9
// speedup vs baseline: 1.2287x; 1.2287x over previous
#include <cuda_runtime.h>
#include <stdint.h>

// embeddings: [B=32, L=4, W=512, D=768] f32; segment_ids: [B=32, W=512] i32 sorted/row.
// Out (f32, concat): word [B, D, W] then sent [B, D].
//
// word[b,d,s] = (1/L) * sum_{w: seg[b,w]==s} sum_l emb[b,l,w,d]
// sent[b,d]   = (1/W) * sum_s word[b,d,s]
//
// R8: decouple DRAM streaming from segment logic. Phase A stores layer-sums
// into tile_w indexed by subword position (plain STS, no aliasing, no carried
// deps -> ptxas keeps ~16 LDG.128 in flight per thread). Phase B (smem-only)
// walks the sorted runs with a register carry and writes each segment total
// to tile_s exactly once.

#define BB 32
#define LL 4
#define WW 512
#define DD 768

#define TILE_S 8           // segments per block
#define CH     16          // subword chunk capacity (avg w-count per block = 8)
#define NTHR   96          // threads per block
#define TILE_D (NTHR * 4)  // 384 d-channels per block (float4/thread)
#define TS_ST  388         // tile_s row stride (floats); odd/4 -> conflict-free transpose

__global__ void zero_sent_kernel(float* __restrict__ sent) {
    int i = blockIdx.x * blockDim.x + threadIdx.x;
    if (i < BB * DD) sent[i] = 0.0f;
}

__device__ __forceinline__ int lower_bound_smem(const int* a, int n, int v) {
    int lo = 0, hi = n;
    while (lo < hi) {
        int m = (lo + hi) >> 1;
        if (a[m] < v) lo = m + 1; else hi = m;
    }
    return lo;
}

__global__ __launch_bounds__(NTHR)
void word_agg_kernel(const float* __restrict__ emb,
                     const int*   __restrict__ seg,
                     float*       __restrict__ word,   // [B, D, W]
                     float*       __restrict__ sent)   // [B, D]
{
    __shared__ float tile_w[CH][TILE_D];      // 16 x 384 x 4B = 24,576 B (by subword)
    __shared__ float tile_s[TILE_S][TS_ST];   //  8 x 388 x 4B = 12,416 B (by segment)
    __shared__ int   segs[WW];                // 2,048 B

    const int b   = blockIdx.z;
    const int s0  = blockIdx.y * TILE_S;
    const int d0  = blockIdx.x * TILE_D;
    const int tid = threadIdx.x;

    #pragma unroll
    for (int i = tid; i < WW; i += NTHR) segs[i] = seg[b * WW + i];

    // Zero tile_s (empty segments must output 0).
    {
        float4* t4 = (float4*)&tile_s[0][0];
        const int n4 = TILE_S * (TS_ST / 4);
        const float4 z = make_float4(0.f, 0.f, 0.f, 0.f);
        for (int i = tid; i < n4; i += NTHR) t4[i] = z;
    }
    __syncthreads();

    const int wlo = lower_bound_smem(segs, WW, s0);
    const int whi = lower_bound_smem(segs, WW, s0 + TILE_S);

    const int d = d0 + tid * 4;
    const float* __restrict__ base = emb + ((size_t)b * LL * WW) * DD + d;
    const size_t LSTRIDE = (size_t)WW * DD;

    // Run-walk state carried ACROSS chunks (a run may straddle a chunk edge).
    int    cur = -1;
    float4 acc = make_float4(0.f, 0.f, 0.f, 0.f);

    for (int w0 = wlo; w0 < whi; w0 += CH) {
        const int nw = min(CH, whi - w0);

        // ---- Phase A: pure streaming, zero dependencies between iterations.
        // Thread tid owns f4-column tid for every j. 4 independent LDG.128
        // per j; unroll keeps ~16 loads in flight per thread.
        #pragma unroll 4
        for (int j = 0; j < nw; ++j) {
            const float* p = base + (size_t)(w0 + j) * DD;
            float4 e0 = *(const float4*)(p);
            float4 e1 = *(const float4*)(p + LSTRIDE);
            float4 e2 = *(const float4*)(p + 2 * LSTRIDE);
            float4 e3 = *(const float4*)(p + 3 * LSTRIDE);
            float4 v;
            v.x = (e0.x + e1.x) + (e2.x + e3.x);
            v.y = (e0.y + e1.y) + (e2.y + e3.y);
            v.z = (e0.z + e1.z) + (e2.z + e3.z);
            v.w = (e0.w + e1.w) + (e2.w + e3.w);
            ((float4*)&tile_w[j][0])[tid] = v;
        }
        __syncthreads();

        // ---- Phase B: smem-only run accumulation. Sorted segs -> each
        // segment row of tile_s is written exactly once (register carry).
        for (int j = 0; j < nw; ++j) {
            const int s = segs[w0 + j];
            if (s != cur) {
                if (cur >= 0) ((float4*)&tile_s[cur - s0][0])[tid] = acc;
                acc = make_float4(0.f, 0.f, 0.f, 0.f);
                cur = s;
            }
            float4 v = ((const float4*)&tile_w[j][0])[tid];
            acc.x += v.x; acc.y += v.y; acc.z += v.z; acc.w += v.w;
        }
        __syncthreads();   // tile_w reusable by next chunk
    }
    if (cur >= 0) ((float4*)&tile_s[cur - s0][0])[tid] = acc;
    __syncthreads();

    // sent contribution: column sum over this s-tile.
    {
        float4 cs = make_float4(0.f, 0.f, 0.f, 0.f);
        #pragma unroll
        for (int s = 0; s < TILE_S; ++s) {
            float4 v = ((const float4*)&tile_s[s][0])[tid];
            cs.x += v.x; cs.y += v.y; cs.z += v.z; cs.w += v.w;
        }
        const float k = 0.25f / (float)WW;
        float* sp = sent + b * DD + d;
        atomicAdd(sp + 0, cs.x * k);
        atomicAdd(sp + 1, cs.y * k);
        atomicAdd(sp + 2, cs.z * k);
        atomicAdd(sp + 3, cs.w * k);
    }

    // Transposed coalesced write: word[b, d0+dd, s0 + ss4*4 .. +3] as float4.
    // ss4 in {0,1}, dd = lane>>1: smem banks of ss4=0/1 groups are disjoint
    // (row stride 388 -> 4*388 % 32 == 16), stores are full 32B sectors.
    float* __restrict__ outb = word + ((size_t)b * DD + d0) * WW + s0;
    const int NOUT = (TILE_S / 4) * TILE_D;   // 768 float4 stores
    for (int i2 = tid; i2 < NOUT; i2 += NTHR) {
        const int ss4 = i2 & 1;
        const int dd  = i2 >> 1;
        float4 v;
        v.x = 0.25f * tile_s[ss4 * 4 + 0][dd];
        v.y = 0.25f * tile_s[ss4 * 4 + 1][dd];
        v.z = 0.25f * tile_s[ss4 * 4 + 2][dd];
        v.w = 0.25f * tile_s[ss4 * 4 + 3][dd];
        *(float4*)(outb + (size_t)dd * WW + ss4 * 4) = v;
    }
}

extern "C" void kernel_launch(void* const* d_in, const int* in_sizes, int n_in,
                              void* d_out, int out_size) {
    const float* emb = (const float*)d_in[0];
    const int*   seg = (const int*)d_in[1];

    float* word = (float*)d_out;                   // [B, D, W]
    float* sent = word + (size_t)BB * DD * WW;     // [B, D]

    zero_sent_kernel<<<(BB * DD + 255) / 256, 256>>>(sent);

    dim3 grid(DD / TILE_D, WW / TILE_S, BB);       // (2, 64, 32) = 4096 blocks
    word_agg_kernel<<<grid, NTHR>>>(emb, seg, word, sent);
}